// round 2
// baseline (speedup 1.0000x reference)
#include <cuda_runtime.h>
#include <cuda_bf16.h>
#include <math.h>
#include <float.h>

#define DIMV 768
#define DEPTH 6
#define HEADS 12
#define DHEAD 64
#define HDV 768
#define PDIMV 192
#define BATCH 2
#define SEQ 1024
#define ROWS (BATCH*SEQ)
#define LN_EPS 1e-5f

// ---------------- scratch (device globals; no runtime allocation) ----------------
__device__ float g_hN[ROWS*DIMV];           // 6.3 MB
__device__ float g_qkv[ROWS*3*HDV];         // 18.9 MB
__device__ float g_q[BATCH*HEADS*SEQ*DHEAD];
__device__ float g_k[BATCH*HEADS*SEQ*DHEAD];
__device__ float g_v[BATCH*HEADS*SEQ*DHEAD];
__device__ float g_o[ROWS*HDV];
__device__ float g_glu[ROWS*8*DIMV];        // 50.3 MB
__device__ float g_gate[ROWS*4*DIMV];       // 25.2 MB
__device__ float g_pbias[(2*SEQ-1)*HEADS];  // [2047, 12]
__device__ float g_temp[BATCH];

// ---------------- dynamic position bias MLP: 1 -> 192 -> 192 -> 12 ----------------
__global__ void posmlp_kernel(const float* __restrict__ pw1, const float* __restrict__ pb1,
                              const float* __restrict__ pw2, const float* __restrict__ pb2,
                              const float* __restrict__ pw3, const float* __restrict__ pb3,
                              float* __restrict__ out)
{
    __shared__ float h1[PDIMV];
    __shared__ float h2[PDIMV];
    int r = blockIdx.x;                    // 0..2046
    float pos = (float)r - (float)(SEQ - 1);
    int t = threadIdx.x;                   // 0..191
    h1[t] = fmaxf(pos * pw1[t] + pb1[t], 0.0f);
    __syncthreads();
    float acc = pb2[t];
    #pragma unroll 4
    for (int k = 0; k < PDIMV; k++) acc += h1[k] * pw2[k*PDIMV + t];
    h2[t] = fmaxf(acc, 0.0f);
    __syncthreads();
    if (t < HEADS) {
        float a = pb3[t];
        #pragma unroll 4
        for (int k = 0; k < PDIMV; k++) a += h2[k] * pw3[k*HEADS + t];
        out[r*HEADS + t] = a;
    }
}

// ---------------- per-batch temperature ----------------
__global__ void temp_kernel(const unsigned char* __restrict__ mask,
                            const float* __restrict__ temperature,
                            float* __restrict__ out)
{
    int b = blockIdx.x;
    __shared__ int sred[8];
    int cnt = 0;
    for (int j = threadIdx.x; j < SEQ; j += blockDim.x)
        cnt += (mask[b*SEQ + j] == 0) ? 1 : 0;
    #pragma unroll
    for (int off = 16; off > 0; off >>= 1) cnt += __shfl_xor_sync(0xffffffffu, cnt, off);
    if ((threadIdx.x & 31) == 0) sred[threadIdx.x >> 5] = cnt;
    __syncthreads();
    if (threadIdx.x == 0) {
        int tot = 0;
        for (int w = 0; w < 8; w++) tot += sred[w];
        float L = (float)tot;
        out[b] = temperature[0] * log2f(L*L - L);
    }
}

// ---------------- LayerNorm (row of 768, block=256) ----------------
__global__ __launch_bounds__(256) void ln_kernel(const float* __restrict__ x,
                                                 const float* __restrict__ g,
                                                 const float* __restrict__ bparm,
                                                 float* __restrict__ out)
{
    int row = blockIdx.x;
    int t = threadIdx.x;
    const float* xr = x + (size_t)row * DIMV;
    float v0 = xr[t], v1 = xr[t + 256], v2 = xr[t + 512];
    float s = v0 + v1 + v2;
    float q = v0*v0 + v1*v1 + v2*v2;
    __shared__ float ss[8], sq[8];
    __shared__ float mean_s, rstd_s;
    #pragma unroll
    for (int off = 16; off > 0; off >>= 1) {
        s += __shfl_xor_sync(0xffffffffu, s, off);
        q += __shfl_xor_sync(0xffffffffu, q, off);
    }
    if ((t & 31) == 0) { ss[t >> 5] = s; sq[t >> 5] = q; }
    __syncthreads();
    if (t == 0) {
        float S = 0.f, Q = 0.f;
        for (int w = 0; w < 8; w++) { S += ss[w]; Q += sq[w]; }
        float mean = S / (float)DIMV;
        float var  = Q / (float)DIMV - mean * mean;
        mean_s = mean;
        rstd_s = rsqrtf(var + LN_EPS);
    }
    __syncthreads();
    float mean = mean_s, rstd = rstd_s;
    float* orow = out + (size_t)row * DIMV;
    orow[t      ] = (v0 - mean) * rstd * g[t      ] + bparm[t      ];
    orow[t + 256] = (v1 - mean) * rstd * g[t + 256] + bparm[t + 256];
    orow[t + 512] = (v2 - mean) * rstd * g[t + 512] + bparm[t + 512];
}

// ---------------- QKV split + L2 norm of q,k -> [B*H, N, 64] layouts ----------------
__global__ __launch_bounds__(128) void qkvnorm_kernel(const float* __restrict__ qkv,
                                                      float* __restrict__ q,
                                                      float* __restrict__ k,
                                                      float* __restrict__ v)
{
    int u = blockIdx.x * 4 + (threadIdx.x >> 5); // (b,n,h) unit
    if (u >= BATCH*SEQ*HEADS) return;
    int lane = threadIdx.x & 31;
    int h = u % HEADS;
    int n = (u / HEADS) % SEQ;
    int b = u / (HEADS * SEQ);
    const float* src = qkv + (size_t)(b*SEQ + n) * (3*HDV) + h * (DHEAD*3);
    float q0 = src[lane*3 + 0],      k0 = src[lane*3 + 1],      v0 = src[lane*3 + 2];
    float q1 = src[(lane+32)*3 + 0], k1 = src[(lane+32)*3 + 1], v1 = src[(lane+32)*3 + 2];
    float qs = q0*q0 + q1*q1;
    float ks = k0*k0 + k1*k1;
    #pragma unroll
    for (int off = 16; off > 0; off >>= 1) {
        qs += __shfl_xor_sync(0xffffffffu, qs, off);
        ks += __shfl_xor_sync(0xffffffffu, ks, off);
    }
    float qi = 1.0f / fmaxf(sqrtf(qs), 1e-12f);
    float ki = 1.0f / fmaxf(sqrtf(ks), 1e-12f);
    size_t base = ((size_t)(b*HEADS + h) * SEQ + n) * DHEAD;
    q[base + lane]      = q0 * qi;
    q[base + lane + 32] = q1 * qi;
    k[base + lane]      = k0 * ki;
    k[base + lane + 32] = k1 * ki;
    v[base + lane]      = v0;
    v[base + lane + 32] = v1;
}

// ---------------- flash attention: BQ=64, BKV=64, 256 thr, 4x4 tiles ----------------
#define ASTRIDE 68
#define SMEM_ATTN (3 * 64 * ASTRIDE * 4)

__global__ __launch_bounds__(256) void attn_kernel(const float* __restrict__ q,
                                                   const float* __restrict__ k,
                                                   const float* __restrict__ v,
                                                   const unsigned char* __restrict__ mask,
                                                   const float* __restrict__ pbias,
                                                   const float* __restrict__ tempv_,
                                                   float* __restrict__ o)
{
    extern __shared__ float sm[];
    float* Qs = sm;
    float* KP = sm + 64 * ASTRIDE;  // K tile, then reused for P
    float* Vs = sm + 2 * 64 * ASTRIDE;

    int bx = blockIdx.x;             // q row tile
    int h  = blockIdx.y;
    int b  = blockIdx.z;
    int bh = b * HEADS + h;
    int q0 = bx * 64;
    int tid = threadIdx.x;
    int ty = tid >> 4, tx = tid & 15;

    const float* qb = q + (size_t)bh * SEQ * DHEAD;
    const float* kb = k + (size_t)bh * SEQ * DHEAD;
    const float* vb = v + (size_t)bh * SEQ * DHEAD;

    #pragma unroll
    for (int it = 0; it < 4; it++) {
        int fi = tid + it * 256;
        int r = fi >> 4, c4 = (fi & 15) * 4;
        *(float4*)&Qs[r*ASTRIDE + c4] = *(const float4*)&qb[(size_t)(q0 + r)*DHEAD + c4];
    }
    float tempv = tempv_[b];
    bool qval[4];
    #pragma unroll
    for (int ii = 0; ii < 4; ii++)
        qval[ii] = (mask[b*SEQ + q0 + 4*ty + ii] == 0);

    float o_acc[4][4];
    float m_prev[4], l_prev[4];
    #pragma unroll
    for (int ii = 0; ii < 4; ii++) {
        m_prev[ii] = -FLT_MAX; l_prev[ii] = 0.f;
        #pragma unroll
        for (int j = 0; j < 4; j++) o_acc[ii][j] = 0.f;
    }
    __syncthreads();

    int ntiles = bx + 1;  // causal: kv tiles 0..bx
    for (int t = 0; t < ntiles; t++) {
        int kv0 = t * 64;
        #pragma unroll
        for (int it = 0; it < 4; it++) {
            int fi = tid + it * 256;
            int r = fi >> 4, c4 = (fi & 15) * 4;
            *(float4*)&KP[r*ASTRIDE + c4] = *(const float4*)&kb[(size_t)(kv0 + r)*DHEAD + c4];
            *(float4*)&Vs[r*ASTRIDE + c4] = *(const float4*)&vb[(size_t)(kv0 + r)*DHEAD + c4];
        }
        __syncthreads();

        // S = Q @ K^T
        float s[4][4] = {};
        #pragma unroll
        for (int d = 0; d < 64; d += 4) {
            float4 qa[4], kk[4];
            #pragma unroll
            for (int ii = 0; ii < 4; ii++) qa[ii] = *(const float4*)&Qs[(4*ty + ii)*ASTRIDE + d];
            #pragma unroll
            for (int jj = 0; jj < 4; jj++) kk[jj] = *(const float4*)&KP[(4*tx + jj)*ASTRIDE + d];
            #pragma unroll
            for (int ii = 0; ii < 4; ii++)
                #pragma unroll
                for (int jj = 0; jj < 4; jj++)
                    s[ii][jj] += qa[ii].x*kk[jj].x + qa[ii].y*kk[jj].y
                               + qa[ii].z*kk[jj].z + qa[ii].w*kk[jj].w;
        }

        // temp * s + bias, then masks
        bool kvalid[4];
        #pragma unroll
        for (int jj = 0; jj < 4; jj++)
            kvalid[jj] = (mask[b*SEQ + kv0 + 4*tx + jj] == 0);
        #pragma unroll
        for (int ii = 0; ii < 4; ii++) {
            int i = q0 + 4*ty + ii;
            #pragma unroll
            for (int jj = 0; jj < 4; jj++) {
                int j = kv0 + 4*tx + jj;
                float sv = s[ii][jj] * tempv + pbias[(i - j + SEQ - 1)*HEADS + h];
                if (j > i || !qval[ii] || !kvalid[jj]) sv = -FLT_MAX;
                s[ii][jj] = sv;
            }
        }

        // online softmax (row groups of 16 lanes within a warp)
        float scale_f[4];
        #pragma unroll
        for (int ii = 0; ii < 4; ii++) {
            float rm = fmaxf(fmaxf(s[ii][0], s[ii][1]), fmaxf(s[ii][2], s[ii][3]));
            #pragma unroll
            for (int off = 8; off > 0; off >>= 1)
                rm = fmaxf(rm, __shfl_xor_sync(0xffffffffu, rm, off));
            float mn = fmaxf(m_prev[ii], rm);
            float rs = 0.f;
            #pragma unroll
            for (int jj = 0; jj < 4; jj++) {
                float p = __expf(s[ii][jj] - mn);
                s[ii][jj] = p;
                rs += p;
            }
            #pragma unroll
            for (int off = 8; off > 0; off >>= 1)
                rs += __shfl_xor_sync(0xffffffffu, rs, off);
            float sc = __expf(m_prev[ii] - mn);
            l_prev[ii] = l_prev[ii]*sc + rs;
            m_prev[ii] = mn;
            scale_f[ii] = sc;
        }

        __syncthreads();           // done reading K
        #pragma unroll
        for (int ii = 0; ii < 4; ii++)
            #pragma unroll
            for (int jj = 0; jj < 4; jj++)
                KP[(4*ty + ii)*ASTRIDE + 4*tx + jj] = s[ii][jj];   // P
        __syncthreads();

        #pragma unroll
        for (int ii = 0; ii < 4; ii++)
            #pragma unroll
            for (int dd = 0; dd < 4; dd++)
                o_acc[ii][dd] *= scale_f[ii];

        // O += P @ V
        #pragma unroll 4
        for (int j = 0; j < 64; j++) {
            float pv[4];
            #pragma unroll
            for (int ii = 0; ii < 4; ii++) pv[ii] = KP[(4*ty + ii)*ASTRIDE + j];
            float4 vv = *(const float4*)&Vs[j*ASTRIDE + 4*tx];
            #pragma unroll
            for (int ii = 0; ii < 4; ii++) {
                o_acc[ii][0] += pv[ii]*vv.x;
                o_acc[ii][1] += pv[ii]*vv.y;
                o_acc[ii][2] += pv[ii]*vv.z;
                o_acc[ii][3] += pv[ii]*vv.w;
            }
        }
        __syncthreads();
    }

    #pragma unroll
    for (int ii = 0; ii < 4; ii++) {
        float inv = 1.0f / l_prev[ii];
        int i = q0 + 4*ty + ii;
        size_t base = (size_t)(b*SEQ + i) * HDV + h*DHEAD + 4*tx;
        o[base + 0] = o_acc[ii][0] * inv;
        o[base + 1] = o_acc[ii][1] * inv;
        o[base + 2] = o_acc[ii][2] * inv;
        o[base + 3] = o_acc[ii][3] * inv;
    }
}

// ---------------- generic SGEMM: C[M,N] = A[M,K] @ B[K,N] (+bias, +res) ----------------
// 128x128 tile, BK=8, 256 threads, 8x8 per thread.
// epi bit0: add bias[col]; epi bit1: add res[row*N+col]
__global__ __launch_bounds__(256) void sgemm_kernel(const float* __restrict__ A,
                                                    const float* __restrict__ B,
                                                    const float* __restrict__ bias,
                                                    const float* __restrict__ res,
                                                    float* __restrict__ C,
                                                    int M, int N, int K, int epi)
{
    __shared__ float As[8][128];
    __shared__ float Bs[8][128];
    int tid = threadIdx.x;
    int row0 = blockIdx.y * 128, col0 = blockIdx.x * 128;
    int arow = tid >> 1, acol = (tid & 1) * 4;
    int brow = tid >> 5, bcol = (tid & 31) * 4;
    const float* Aptr = A + (size_t)(row0 + arow) * K + acol;
    const float* Bptr = B + (size_t)brow * N + col0 + bcol;
    float acc[8][8] = {};
    int tr = (tid >> 4) * 8, tc = (tid & 15) * 8;

    for (int k0 = 0; k0 < K; k0 += 8) {
        float4 av = *(const float4*)(Aptr + k0);
        As[acol + 0][arow] = av.x;
        As[acol + 1][arow] = av.y;
        As[acol + 2][arow] = av.z;
        As[acol + 3][arow] = av.w;
        *(float4*)&Bs[brow][bcol] = *(const float4*)(Bptr + (size_t)k0 * N);
        __syncthreads();
        #pragma unroll
        for (int kk = 0; kk < 8; kk++) {
            float a[8], bb[8];
            *(float4*)(a)     = *(const float4*)&As[kk][tr];
            *(float4*)(a + 4) = *(const float4*)&As[kk][tr + 4];
            *(float4*)(bb)     = *(const float4*)&Bs[kk][tc];
            *(float4*)(bb + 4) = *(const float4*)&Bs[kk][tc + 4];
            #pragma unroll
            for (int i = 0; i < 8; i++)
                #pragma unroll
                for (int j = 0; j < 8; j++)
                    acc[i][j] += a[i] * bb[j];
        }
        __syncthreads();
    }

    #pragma unroll
    for (int i = 0; i < 8; i++) {
        int r = row0 + tr + i;
        size_t rb = (size_t)r * N + col0 + tc;
        #pragma unroll
        for (int j = 0; j < 8; j++) {
            float vv = acc[i][j];
            if (epi & 1) vv += bias[col0 + tc + j];
            if (epi & 2) vv += res[rb + j];
            C[rb + j] = vv;
        }
    }
}

// ---------------- GLU gating: out = a * silu(g) ----------------
__global__ void glu_gate_kernel(const float* __restrict__ p, float* __restrict__ out)
{
    int idx = blockIdx.x * blockDim.x + threadIdx.x;
    if (idx >= ROWS * 4 * DIMV) return;
    int row = idx / (4 * DIMV);
    int c   = idx % (4 * DIMV);
    float a = p[(size_t)row * (8 * DIMV) + c];
    float g = p[(size_t)row * (8 * DIMV) + 4 * DIMV + c];
    out[idx] = a * (g / (1.0f + __expf(-g)));
}

// ---------------- host launcher ----------------
extern "C" void kernel_launch(void* const* d_in, const int* in_sizes, int n_in,
                              void* d_out, int out_size)
{
    const float* x_in          = (const float*)d_in[0];
    const unsigned char* mask  = (const unsigned char*)d_in[1];
    const float* temperature   = (const float*)d_in[2];
    const float* pw1 = (const float*)d_in[3];
    const float* pb1 = (const float*)d_in[4];
    const float* pw2 = (const float*)d_in[5];
    const float* pb2 = (const float*)d_in[6];
    const float* pw3 = (const float*)d_in[7];
    const float* pb3 = (const float*)d_in[8];
    const float* ln1_g = (const float*)d_in[9];
    const float* ln1_b = (const float*)d_in[10];
    const float* qkv_w = (const float*)d_in[11];
    const float* out_w = (const float*)d_in[12];
    const float* ln2_g = (const float*)d_in[13];
    const float* ln2_b = (const float*)d_in[14];
    const float* glu_w = (const float*)d_in[15];
    const float* glu_b = (const float*)d_in[16];
    const float* ff2_w = (const float*)d_in[17];
    const float* ff2_b = (const float*)d_in[18];
    float* x = (float*)d_out;

    float *hN, *qkvbuf, *qb, *kb, *vb, *ob, *glubuf, *gatebuf, *pbias, *tempbuf;
    cudaGetSymbolAddress((void**)&hN,      g_hN);
    cudaGetSymbolAddress((void**)&qkvbuf,  g_qkv);
    cudaGetSymbolAddress((void**)&qb,      g_q);
    cudaGetSymbolAddress((void**)&kb,      g_k);
    cudaGetSymbolAddress((void**)&vb,      g_v);
    cudaGetSymbolAddress((void**)&ob,      g_o);
    cudaGetSymbolAddress((void**)&glubuf,  g_glu);
    cudaGetSymbolAddress((void**)&gatebuf, g_gate);
    cudaGetSymbolAddress((void**)&pbias,   g_pbias);
    cudaGetSymbolAddress((void**)&tempbuf, g_temp);

    cudaFuncSetAttribute(attn_kernel, cudaFuncAttributeMaxDynamicSharedMemorySize, SMEM_ATTN);

    // residual stream lives in d_out
    cudaMemcpyAsync(x, x_in, sizeof(float) * ROWS * DIMV, cudaMemcpyDeviceToDevice, 0);

    posmlp_kernel<<<2*SEQ - 1, PDIMV>>>(pw1, pb1, pw2, pb2, pw3, pb3, pbias);
    temp_kernel<<<BATCH, 256>>>(mask, temperature, tempbuf);

    for (int i = 0; i < DEPTH; i++) {
        // --- attention block ---
        ln_kernel<<<ROWS, 256>>>(x, ln1_g + i*DIMV, ln1_b + i*DIMV, hN);
        sgemm_kernel<<<dim3(3*HDV/128, ROWS/128), 256>>>(
            hN, qkv_w + (size_t)i*DIMV*3*HDV, nullptr, nullptr, qkvbuf,
            ROWS, 3*HDV, DIMV, 0);
        qkvnorm_kernel<<<(BATCH*SEQ*HEADS + 3)/4, 128>>>(qkvbuf, qb, kb, vb);
        attn_kernel<<<dim3(SEQ/64, HEADS, BATCH), 256, SMEM_ATTN>>>(
            qb, kb, vb, mask, pbias, tempbuf, ob);
        sgemm_kernel<<<dim3(DIMV/128, ROWS/128), 256>>>(
            ob, out_w + (size_t)i*HDV*DIMV, nullptr, x, x,
            ROWS, DIMV, HDV, 2);
        // --- GLU FFN block ---
        ln_kernel<<<ROWS, 256>>>(x, ln2_g + i*DIMV, ln2_b + i*DIMV, hN);
        sgemm_kernel<<<dim3(8*DIMV/128, ROWS/128), 256>>>(
            hN, glu_w + (size_t)i*DIMV*8*DIMV, glu_b + (size_t)i*8*DIMV, nullptr, glubuf,
            ROWS, 8*DIMV, DIMV, 1);
        glu_gate_kernel<<<(ROWS*4*DIMV + 255)/256, 256>>>(glubuf, gatebuf);
        sgemm_kernel<<<dim3(DIMV/128, ROWS/128), 256>>>(
            gatebuf, ff2_w + (size_t)i*4*DIMV*DIMV, ff2_b + (size_t)i*DIMV, x, x,
            ROWS, DIMV, 4*DIMV, 3);
    }
}

// round 6
// speedup vs baseline: 2.2474x; 2.2474x over previous
#include <cuda_runtime.h>
#include <cuda_bf16.h>
#include <math.h>
#include <float.h>
#include <stdint.h>

#define DIMV 768
#define DEPTH 6
#define HEADS 12
#define DHEAD 64
#define HDV 768
#define PDIMV 192
#define BATCH 2
#define SEQ 1024
#define ROWS (BATCH*SEQ)
#define LN_EPS 1e-5f

// ================= scratch (device globals) =================
__device__ float g_qkv[ROWS*3*HDV];
__device__ float g_q[BATCH*HEADS*SEQ*DHEAD];
__device__ float g_k[BATCH*HEADS*SEQ*DHEAD];
__device__ float g_v[BATCH*HEADS*SEQ*DHEAD];
__device__ float g_glu[ROWS*8*DIMV];
__device__ float g_pbias[(2*SEQ-1)*HEADS];
__device__ float g_temp[BATCH];

// bf16 hi/lo activation buffers
__device__ __nv_bfloat16 g_hN_hi[ROWS*DIMV],     g_hN_lo[ROWS*DIMV];
__device__ __nv_bfloat16 g_o_hi[ROWS*HDV],       g_o_lo[ROWS*HDV];
__device__ __nv_bfloat16 g_gate_hi[ROWS*4*DIMV], g_gate_lo[ROWS*4*DIMV];

// bf16 hi/lo transposed weights  W[K,N] -> Wt[N,K]
__device__ __nv_bfloat16 g_wqkv_hi[DEPTH*3*HDV*DIMV], g_wqkv_lo[DEPTH*3*HDV*DIMV];
__device__ __nv_bfloat16 g_wout_hi[DEPTH*DIMV*HDV],   g_wout_lo[DEPTH*DIMV*HDV];
__device__ __nv_bfloat16 g_wglu_hi[DEPTH*8*DIMV*DIMV], g_wglu_lo[DEPTH*8*DIMV*DIMV];
__device__ __nv_bfloat16 g_wff2_hi[DEPTH*4*DIMV*DIMV], g_wff2_lo[DEPTH*4*DIMV*DIMV];

// ================= PTX helpers (compute_103-safe: no tcgen05) =================
__device__ __forceinline__ uint32_t smem_u32(const void* p){
    uint32_t a;
    asm("{ .reg .u64 t; cvta.to.shared.u64 t, %1; cvt.u32.u64 %0, t; }" : "=r"(a) : "l"(p));
    return a;
}
__device__ __forceinline__ void cp_async16(uint32_t dst, const void* src){
    asm volatile("cp.async.cg.shared.global [%0], [%1], 16;" :: "r"(dst), "l"(src));
}
__device__ __forceinline__ void cp_commit(){ asm volatile("cp.async.commit_group;"); }
__device__ __forceinline__ void cp_wait0(){ asm volatile("cp.async.wait_group 0;" ::: "memory"); }
__device__ __forceinline__ void cp_wait1(){ asm volatile("cp.async.wait_group 1;" ::: "memory"); }

__device__ __forceinline__ void ldsm4(uint32_t* r, uint32_t a){
    asm volatile("ldmatrix.sync.aligned.m8n8.x4.shared.b16 {%0,%1,%2,%3}, [%4];"
        : "=r"(r[0]), "=r"(r[1]), "=r"(r[2]), "=r"(r[3]) : "r"(a));
}
__device__ __forceinline__ void mma_bf16(float* d, const uint32_t* a, uint32_t b0, uint32_t b1){
    asm volatile("mma.sync.aligned.m16n8k16.row.col.f32.bf16.bf16.f32 "
        "{%0,%1,%2,%3}, {%4,%5,%6,%7}, {%8,%9}, {%0,%1,%2,%3};"
        : "+f"(d[0]), "+f"(d[1]), "+f"(d[2]), "+f"(d[3])
        : "r"(a[0]), "r"(a[1]), "r"(a[2]), "r"(a[3]), "r"(b0), "r"(b1));
}
__device__ __forceinline__ void bsplit(float v, __nv_bfloat16* hi, __nv_bfloat16* lo){
    __nv_bfloat16 h = __float2bfloat16(v);
    *hi = h;
    *lo = __float2bfloat16(v - __bfloat162float(h));
}

// ================= weight transpose + bf16 split: W[K,N] -> hi/lo[N,K] =================
__global__ __launch_bounds__(256) void wconv_kernel(const float* __restrict__ W,
                                                    __nv_bfloat16* __restrict__ hi,
                                                    __nv_bfloat16* __restrict__ lo,
                                                    int K, int N)
{
    __shared__ float t[32][33];
    int z = blockIdx.z;
    const float* Wl = W + (size_t)z * K * N;
    __nv_bfloat16* hil = hi + (size_t)z * N * K;
    __nv_bfloat16* lol = lo + (size_t)z * N * K;
    int n0 = blockIdx.x * 32, k0 = blockIdx.y * 32;
    int tx = threadIdx.x & 31, ty = threadIdx.x >> 5;
    #pragma unroll
    for (int i = 0; i < 4; i++)
        t[ty + 8*i][tx] = Wl[(size_t)(k0 + ty + 8*i) * N + n0 + tx];
    __syncthreads();
    #pragma unroll
    for (int i = 0; i < 4; i++) {
        float v = t[tx][ty + 8*i];
        size_t o = (size_t)(n0 + ty + 8*i) * K + k0 + tx;
        __nv_bfloat16 h, l;
        bsplit(v, &h, &l);
        hil[o] = h; lol[o] = l;
    }
}

// ================= HMMA GEMM: C[M,N] = A[M,K] @ Bt[N,K]^T (+bias,+res) =================
// A,Bt bf16 hi/lo K-major. 3-product split into fp32 mma accumulators.
// CTA 128x128, BK=64, 8 warps each 64(m) x 32(n), double-buffered cp.async.
#define BK 64
#define AS_B 144                        // padded row stride in bytes (72 bf16)
#define TILE_B (128*AS_B)               // 18432
#define STAGE_B (4*TILE_B)              // 73728
#define GSMEM (2*STAGE_B)               // 147456

__device__ __forceinline__ void load_tile(uint32_t dstbase, const __nv_bfloat16* src,
                                          int rbase, int K, int kb, int tid)
{
    const char* s0 = (const char*)src + ((size_t)rbase * K + kb) * 2;
    #pragma unroll
    for (int i = 0; i < 4; i++) {
        int f = tid + i * 256;
        int r = f >> 3, j = f & 7;
        cp_async16(dstbase + r * AS_B + j * 16, s0 + (size_t)r * K * 2 + j * 16);
    }
}

__global__ __launch_bounds__(256, 1) void tc_gemm(const __nv_bfloat16* __restrict__ Ahi,
                                                  const __nv_bfloat16* __restrict__ Alo,
                                                  const __nv_bfloat16* __restrict__ Bhi,
                                                  const __nv_bfloat16* __restrict__ Blo,
                                                  const float* __restrict__ bias,
                                                  const float* __restrict__ res,
                                                  float* __restrict__ C,
                                                  int N, int K, int epi)
{
    extern __shared__ char sm[];
    uint32_t smb = smem_u32(sm);
    int tid = threadIdx.x, wid = tid >> 5, l = tid & 31;
    int row0 = blockIdx.y * 128, col0 = blockIdx.x * 128;
    int wr = wid & 1, wc = wid >> 1;       // warp tile: rows wr*64, cols wc*32

    float acc[4][4][4];
    #pragma unroll
    for (int a = 0; a < 4; a++)
        #pragma unroll
        for (int b = 0; b < 4; b++)
            #pragma unroll
            for (int c = 0; c < 4; c++) acc[a][b][c] = 0.f;

    // per-thread ldmatrix offsets (within a tile)
    uint32_t offA[4], offB[2];
    #pragma unroll
    for (int mt = 0; mt < 4; mt++)
        offA[mt] = (uint32_t)(wr*64 + mt*16 + (l & 15)) * AS_B + (l >> 4) * 16;
    #pragma unroll
    for (int h = 0; h < 2; h++)
        offB[h] = (uint32_t)(wc*32 + h*16 + (l & 15)) * AS_B + (l >> 4) * 16;

    int nc = K / BK;
    {   // prologue -> stage 0
        uint32_t sb = smb;
        load_tile(sb + 0*TILE_B, Ahi, row0, K, 0, tid);
        load_tile(sb + 1*TILE_B, Alo, row0, K, 0, tid);
        load_tile(sb + 2*TILE_B, Bhi, col0, K, 0, tid);
        load_tile(sb + 3*TILE_B, Blo, col0, K, 0, tid);
        cp_commit();
    }

    for (int c = 0; c < nc; c++) {
        int s = c & 1;
        if (c + 1 < nc) {
            uint32_t sb = smb + (1 - s) * STAGE_B;
            int kb = (c + 1) * BK;
            load_tile(sb + 0*TILE_B, Ahi, row0, K, kb, tid);
            load_tile(sb + 1*TILE_B, Alo, row0, K, kb, tid);
            load_tile(sb + 2*TILE_B, Bhi, col0, K, kb, tid);
            load_tile(sb + 3*TILE_B, Blo, col0, K, kb, tid);
            cp_commit();
            cp_wait1();
        } else {
            cp_wait0();
        }
        __syncthreads();

        uint32_t sb = smb + s * STAGE_B;
        #pragma unroll
        for (int ks = 0; ks < 4; ks++) {
            uint32_t kofs = ks * 32;
            uint32_t ah[4][4], al[4][4], bh[2][4], bl[2][4];
            #pragma unroll
            for (int mt = 0; mt < 4; mt++) ldsm4(ah[mt], sb + 0*TILE_B + offA[mt] + kofs);
            #pragma unroll
            for (int mt = 0; mt < 4; mt++) ldsm4(al[mt], sb + 1*TILE_B + offA[mt] + kofs);
            #pragma unroll
            for (int h = 0; h < 2; h++)    ldsm4(bh[h], sb + 2*TILE_B + offB[h] + kofs);
            #pragma unroll
            for (int h = 0; h < 2; h++)    ldsm4(bl[h], sb + 3*TILE_B + offB[h] + kofs);

            #pragma unroll
            for (int mt = 0; mt < 4; mt++) {
                #pragma unroll
                for (int nt = 0; nt < 4; nt++) {
                    int h = nt >> 1, sel = nt & 1;
                    uint32_t bh0 = bh[h][sel], bh1 = bh[h][sel + 2];
                    uint32_t bl0 = bl[h][sel], bl1 = bl[h][sel + 2];
                    mma_bf16(acc[mt][nt], ah[mt], bh0, bh1);
                    mma_bf16(acc[mt][nt], ah[mt], bl0, bl1);
                    mma_bf16(acc[mt][nt], al[mt], bh0, bh1);
                }
            }
        }
        __syncthreads();
    }

    // epilogue: fragment layout -> global
    int g = l >> 2, t4 = l & 3;
    #pragma unroll
    for (int mt = 0; mt < 4; mt++) {
        int r0 = row0 + wr*64 + mt*16 + g;
        #pragma unroll
        for (int nt = 0; nt < 4; nt++) {
            int col = col0 + wc*32 + nt*8 + t4*2;
            float2 v0 = make_float2(acc[mt][nt][0], acc[mt][nt][1]);
            float2 v1 = make_float2(acc[mt][nt][2], acc[mt][nt][3]);
            if (epi & 1) {
                float2 bv = *(const float2*)&bias[col];
                v0.x += bv.x; v0.y += bv.y;
                v1.x += bv.x; v1.y += bv.y;
            }
            size_t b0 = (size_t)r0 * N + col;
            size_t b1 = (size_t)(r0 + 8) * N + col;
            if (epi & 2) {
                float2 r0v = *(const float2*)&res[b0];
                float2 r1v = *(const float2*)&res[b1];
                v0.x += r0v.x; v0.y += r0v.y;
                v1.x += r1v.x; v1.y += r1v.y;
            }
            *(float2*)&C[b0] = v0;
            *(float2*)&C[b1] = v1;
        }
    }
}

// ================= position bias MLP =================
__global__ void posmlp_kernel(const float* __restrict__ pw1, const float* __restrict__ pb1,
                              const float* __restrict__ pw2, const float* __restrict__ pb2,
                              const float* __restrict__ pw3, const float* __restrict__ pb3,
                              float* __restrict__ out)
{
    __shared__ float h1[PDIMV];
    __shared__ float h2[PDIMV];
    int r = blockIdx.x;
    float pos = (float)r - (float)(SEQ - 1);
    int t = threadIdx.x;
    h1[t] = fmaxf(pos * pw1[t] + pb1[t], 0.0f);
    __syncthreads();
    float acc = pb2[t];
    #pragma unroll 4
    for (int k = 0; k < PDIMV; k++) acc += h1[k] * pw2[k*PDIMV + t];
    h2[t] = fmaxf(acc, 0.0f);
    __syncthreads();
    if (t < HEADS) {
        float a = pb3[t];
        #pragma unroll 4
        for (int k = 0; k < PDIMV; k++) a += h2[k] * pw3[k*HEADS + t];
        out[r*HEADS + t] = a;
    }
}

// ================= per-batch temperature =================
__global__ void temp_kernel(const unsigned char* __restrict__ mask,
                            const float* __restrict__ temperature,
                            float* __restrict__ out)
{
    int b = blockIdx.x;
    __shared__ int sred[8];
    int cnt = 0;
    for (int j = threadIdx.x; j < SEQ; j += blockDim.x)
        cnt += (mask[b*SEQ + j] == 0) ? 1 : 0;
    #pragma unroll
    for (int off = 16; off > 0; off >>= 1) cnt += __shfl_xor_sync(0xffffffffu, cnt, off);
    if ((threadIdx.x & 31) == 0) sred[threadIdx.x >> 5] = cnt;
    __syncthreads();
    if (threadIdx.x == 0) {
        int tot = 0;
        for (int w = 0; w < 8; w++) tot += sred[w];
        float L = (float)tot;
        out[b] = temperature[0] * log2f(L*L - L);
    }
}

// ================= LayerNorm -> bf16 hi/lo =================
__global__ __launch_bounds__(256) void ln_kernel(const float* __restrict__ x,
                                                 const float* __restrict__ g,
                                                 const float* __restrict__ bparm,
                                                 __nv_bfloat16* __restrict__ ohi,
                                                 __nv_bfloat16* __restrict__ olo)
{
    int row = blockIdx.x;
    int t = threadIdx.x;
    const float* xr = x + (size_t)row * DIMV;
    float v0 = xr[t], v1 = xr[t + 256], v2 = xr[t + 512];
    float s = v0 + v1 + v2;
    float q = v0*v0 + v1*v1 + v2*v2;
    __shared__ float ss[8], sq[8];
    __shared__ float mean_s, rstd_s;
    #pragma unroll
    for (int off = 16; off > 0; off >>= 1) {
        s += __shfl_xor_sync(0xffffffffu, s, off);
        q += __shfl_xor_sync(0xffffffffu, q, off);
    }
    if ((t & 31) == 0) { ss[t >> 5] = s; sq[t >> 5] = q; }
    __syncthreads();
    if (t == 0) {
        float S = 0.f, Q = 0.f;
        for (int w = 0; w < 8; w++) { S += ss[w]; Q += sq[w]; }
        float mean = S / (float)DIMV;
        float var  = Q / (float)DIMV - mean * mean;
        mean_s = mean;
        rstd_s = rsqrtf(var + LN_EPS);
    }
    __syncthreads();
    float mean = mean_s, rstd = rstd_s;
    size_t rb = (size_t)row * DIMV;
    #pragma unroll
    for (int u = 0; u < 3; u++) {
        int c = t + u * 256;
        float vv = (u == 0 ? v0 : (u == 1 ? v1 : v2));
        float val = (vv - mean) * rstd * g[c] + bparm[c];
        __nv_bfloat16 h, lo;
        bsplit(val, &h, &lo);
        ohi[rb + c] = h; olo[rb + c] = lo;
    }
}

// ================= QKV split + L2 norm =================
__global__ __launch_bounds__(128) void qkvnorm_kernel(const float* __restrict__ qkv,
                                                      float* __restrict__ q,
                                                      float* __restrict__ k,
                                                      float* __restrict__ v)
{
    int u = blockIdx.x * 4 + (threadIdx.x >> 5);
    if (u >= BATCH*SEQ*HEADS) return;
    int lane = threadIdx.x & 31;
    int h = u % HEADS;
    int n = (u / HEADS) % SEQ;
    int b = u / (HEADS * SEQ);
    const float* src = qkv + (size_t)(b*SEQ + n) * (3*HDV) + h * (DHEAD*3);
    float q0 = src[lane*3 + 0],      k0 = src[lane*3 + 1],      v0 = src[lane*3 + 2];
    float q1 = src[(lane+32)*3 + 0], k1 = src[(lane+32)*3 + 1], v1 = src[(lane+32)*3 + 2];
    float qs = q0*q0 + q1*q1;
    float ks = k0*k0 + k1*k1;
    #pragma unroll
    for (int off = 16; off > 0; off >>= 1) {
        qs += __shfl_xor_sync(0xffffffffu, qs, off);
        ks += __shfl_xor_sync(0xffffffffu, ks, off);
    }
    float qi = 1.0f / fmaxf(sqrtf(qs), 1e-12f);
    float ki = 1.0f / fmaxf(sqrtf(ks), 1e-12f);
    size_t base = ((size_t)(b*HEADS + h) * SEQ + n) * DHEAD;
    q[base + lane]      = q0 * qi;
    q[base + lane + 32] = q1 * qi;
    k[base + lane]      = k0 * ki;
    k[base + lane + 32] = k1 * ki;
    v[base + lane]      = v0;
    v[base + lane + 32] = v1;
}

// ================= flash attention (epilogue -> bf16 hi/lo) =================
#define ASTRIDE 68
#define SMEM_ATTN (3 * 64 * ASTRIDE * 4)

__global__ __launch_bounds__(256) void attn_kernel(const float* __restrict__ q,
                                                   const float* __restrict__ k,
                                                   const float* __restrict__ v,
                                                   const unsigned char* __restrict__ mask,
                                                   const float* __restrict__ pbias,
                                                   const float* __restrict__ tempv_,
                                                   __nv_bfloat16* __restrict__ ohi,
                                                   __nv_bfloat16* __restrict__ olo)
{
    extern __shared__ float smf[];
    float* Qs = smf;
    float* KP = smf + 64 * ASTRIDE;
    float* Vs = smf + 2 * 64 * ASTRIDE;

    int bx = blockIdx.x;
    int h  = blockIdx.y;
    int b  = blockIdx.z;
    int bh = b * HEADS + h;
    int q0 = bx * 64;
    int tid = threadIdx.x;
    int ty = tid >> 4, tx = tid & 15;

    const float* qb = q + (size_t)bh * SEQ * DHEAD;
    const float* kb = k + (size_t)bh * SEQ * DHEAD;
    const float* vb = v + (size_t)bh * SEQ * DHEAD;

    #pragma unroll
    for (int it = 0; it < 4; it++) {
        int fi = tid + it * 256;
        int r = fi >> 4, c4 = (fi & 15) * 4;
        *(float4*)&Qs[r*ASTRIDE + c4] = *(const float4*)&qb[(size_t)(q0 + r)*DHEAD + c4];
    }
    float tempv = tempv_[b];
    bool qval[4];
    #pragma unroll
    for (int ii = 0; ii < 4; ii++)
        qval[ii] = (mask[b*SEQ + q0 + 4*ty + ii] == 0);

    float o_acc[4][4];
    float m_prev[4], l_prev[4];
    #pragma unroll
    for (int ii = 0; ii < 4; ii++) {
        m_prev[ii] = -FLT_MAX; l_prev[ii] = 0.f;
        #pragma unroll
        for (int j = 0; j < 4; j++) o_acc[ii][j] = 0.f;
    }
    __syncthreads();

    int ntiles = bx + 1;
    for (int t = 0; t < ntiles; t++) {
        int kv0 = t * 64;
        #pragma unroll
        for (int it = 0; it < 4; it++) {
            int fi = tid + it * 256;
            int r = fi >> 4, c4 = (fi & 15) * 4;
            *(float4*)&KP[r*ASTRIDE + c4] = *(const float4*)&kb[(size_t)(kv0 + r)*DHEAD + c4];
            *(float4*)&Vs[r*ASTRIDE + c4] = *(const float4*)&vb[(size_t)(kv0 + r)*DHEAD + c4];
        }
        __syncthreads();

        float s[4][4] = {};
        #pragma unroll
        for (int d = 0; d < 64; d += 4) {
            float4 qa[4], kk[4];
            #pragma unroll
            for (int ii = 0; ii < 4; ii++) qa[ii] = *(const float4*)&Qs[(4*ty + ii)*ASTRIDE + d];
            #pragma unroll
            for (int jj = 0; jj < 4; jj++) kk[jj] = *(const float4*)&KP[(4*tx + jj)*ASTRIDE + d];
            #pragma unroll
            for (int ii = 0; ii < 4; ii++)
                #pragma unroll
                for (int jj = 0; jj < 4; jj++)
                    s[ii][jj] += qa[ii].x*kk[jj].x + qa[ii].y*kk[jj].y
                               + qa[ii].z*kk[jj].z + qa[ii].w*kk[jj].w;
        }

        bool kvalid[4];
        #pragma unroll
        for (int jj = 0; jj < 4; jj++)
            kvalid[jj] = (mask[b*SEQ + kv0 + 4*tx + jj] == 0);
        #pragma unroll
        for (int ii = 0; ii < 4; ii++) {
            int i = q0 + 4*ty + ii;
            #pragma unroll
            for (int jj = 0; jj < 4; jj++) {
                int j = kv0 + 4*tx + jj;
                float sv = s[ii][jj] * tempv + pbias[(i - j + SEQ - 1)*HEADS + h];
                if (j > i || !qval[ii] || !kvalid[jj]) sv = -FLT_MAX;
                s[ii][jj] = sv;
            }
        }

        float scale_f[4];
        #pragma unroll
        for (int ii = 0; ii < 4; ii++) {
            float rm = fmaxf(fmaxf(s[ii][0], s[ii][1]), fmaxf(s[ii][2], s[ii][3]));
            #pragma unroll
            for (int off = 8; off > 0; off >>= 1)
                rm = fmaxf(rm, __shfl_xor_sync(0xffffffffu, rm, off));
            float mn = fmaxf(m_prev[ii], rm);
            float rs = 0.f;
            #pragma unroll
            for (int jj = 0; jj < 4; jj++) {
                float p = __expf(s[ii][jj] - mn);
                s[ii][jj] = p;
                rs += p;
            }
            #pragma unroll
            for (int off = 8; off > 0; off >>= 1)
                rs += __shfl_xor_sync(0xffffffffu, rs, off);
            float sc = __expf(m_prev[ii] - mn);
            l_prev[ii] = l_prev[ii]*sc + rs;
            m_prev[ii] = mn;
            scale_f[ii] = sc;
        }

        __syncthreads();
        #pragma unroll
        for (int ii = 0; ii < 4; ii++)
            #pragma unroll
            for (int jj = 0; jj < 4; jj++)
                KP[(4*ty + ii)*ASTRIDE + 4*tx + jj] = s[ii][jj];
        __syncthreads();

        #pragma unroll
        for (int ii = 0; ii < 4; ii++)
            #pragma unroll
            for (int dd = 0; dd < 4; dd++)
                o_acc[ii][dd] *= scale_f[ii];

        #pragma unroll 4
        for (int j = 0; j < 64; j++) {
            float pv[4];
            #pragma unroll
            for (int ii = 0; ii < 4; ii++) pv[ii] = KP[(4*ty + ii)*ASTRIDE + j];
            float4 vv = *(const float4*)&Vs[j*ASTRIDE + 4*tx];
            #pragma unroll
            for (int ii = 0; ii < 4; ii++) {
                o_acc[ii][0] += pv[ii]*vv.x;
                o_acc[ii][1] += pv[ii]*vv.y;
                o_acc[ii][2] += pv[ii]*vv.z;
                o_acc[ii][3] += pv[ii]*vv.w;
            }
        }
        __syncthreads();
    }

    #pragma unroll
    for (int ii = 0; ii < 4; ii++) {
        float inv = 1.0f / l_prev[ii];
        int i = q0 + 4*ty + ii;
        size_t base = (size_t)(b*SEQ + i) * HDV + h*DHEAD + 4*tx;
        #pragma unroll
        for (int jj = 0; jj < 4; jj++) {
            float val = o_acc[ii][jj] * inv;
            __nv_bfloat16 hh, ll;
            bsplit(val, &hh, &ll);
            ohi[base + jj] = hh; olo[base + jj] = ll;
        }
    }
}

// ================= GLU gating -> bf16 hi/lo =================
__global__ void glu_gate_kernel(const float* __restrict__ p,
                                __nv_bfloat16* __restrict__ ohi,
                                __nv_bfloat16* __restrict__ olo)
{
    int idx = blockIdx.x * blockDim.x + threadIdx.x;
    if (idx >= ROWS * 4 * DIMV) return;
    int row = idx / (4 * DIMV);
    int c   = idx % (4 * DIMV);
    float a = p[(size_t)row * (8 * DIMV) + c];
    float g = p[(size_t)row * (8 * DIMV) + 4 * DIMV + c];
    float val = a * (g / (1.0f + __expf(-g)));
    __nv_bfloat16 h, l;
    bsplit(val, &h, &l);
    ohi[idx] = h; olo[idx] = l;
}

// ================= host launcher =================
extern "C" void kernel_launch(void* const* d_in, const int* in_sizes, int n_in,
                              void* d_out, int out_size)
{
    const float* x_in          = (const float*)d_in[0];
    const unsigned char* mask  = (const unsigned char*)d_in[1];
    const float* temperature   = (const float*)d_in[2];
    const float* pw1 = (const float*)d_in[3];
    const float* pb1 = (const float*)d_in[4];
    const float* pw2 = (const float*)d_in[5];
    const float* pb2 = (const float*)d_in[6];
    const float* pw3 = (const float*)d_in[7];
    const float* pb3 = (const float*)d_in[8];
    const float* ln1_g = (const float*)d_in[9];
    const float* ln1_b = (const float*)d_in[10];
    const float* qkv_w = (const float*)d_in[11];
    const float* out_w = (const float*)d_in[12];
    const float* ln2_g = (const float*)d_in[13];
    const float* ln2_b = (const float*)d_in[14];
    const float* glu_w = (const float*)d_in[15];
    const float* glu_b = (const float*)d_in[16];
    const float* ff2_w = (const float*)d_in[17];
    const float* ff2_b = (const float*)d_in[18];
    float* x = (float*)d_out;

    float *qkvbuf, *qb, *kb, *vb, *glubuf, *pbias, *tempbuf;
    cudaGetSymbolAddress((void**)&qkvbuf,  g_qkv);
    cudaGetSymbolAddress((void**)&qb,      g_q);
    cudaGetSymbolAddress((void**)&kb,      g_k);
    cudaGetSymbolAddress((void**)&vb,      g_v);
    cudaGetSymbolAddress((void**)&glubuf,  g_glu);
    cudaGetSymbolAddress((void**)&pbias,   g_pbias);
    cudaGetSymbolAddress((void**)&tempbuf, g_temp);

    __nv_bfloat16 *hNh, *hNl, *oh, *ol, *gh, *gl;
    __nv_bfloat16 *wqh, *wql, *woh, *wol, *wgh, *wgl, *wfh, *wfl;
    cudaGetSymbolAddress((void**)&hNh, g_hN_hi);
    cudaGetSymbolAddress((void**)&hNl, g_hN_lo);
    cudaGetSymbolAddress((void**)&oh,  g_o_hi);
    cudaGetSymbolAddress((void**)&ol,  g_o_lo);
    cudaGetSymbolAddress((void**)&gh,  g_gate_hi);
    cudaGetSymbolAddress((void**)&gl,  g_gate_lo);
    cudaGetSymbolAddress((void**)&wqh, g_wqkv_hi);
    cudaGetSymbolAddress((void**)&wql, g_wqkv_lo);
    cudaGetSymbolAddress((void**)&woh, g_wout_hi);
    cudaGetSymbolAddress((void**)&wol, g_wout_lo);
    cudaGetSymbolAddress((void**)&wgh, g_wglu_hi);
    cudaGetSymbolAddress((void**)&wgl, g_wglu_lo);
    cudaGetSymbolAddress((void**)&wfh, g_wff2_hi);
    cudaGetSymbolAddress((void**)&wfl, g_wff2_lo);

    cudaFuncSetAttribute(attn_kernel, cudaFuncAttributeMaxDynamicSharedMemorySize, SMEM_ATTN);
    cudaFuncSetAttribute(tc_gemm,     cudaFuncAttributeMaxDynamicSharedMemorySize, GSMEM);

    // residual stream lives in d_out
    cudaMemcpyAsync(x, x_in, sizeof(float) * ROWS * DIMV, cudaMemcpyDeviceToDevice, 0);

    // one-time (per launch) weight transpose + bf16 split
    wconv_kernel<<<dim3(3*HDV/32, DIMV/32, DEPTH), 256>>>(qkv_w, wqh, wql, DIMV, 3*HDV);
    wconv_kernel<<<dim3(DIMV/32, HDV/32, DEPTH), 256>>>(out_w, woh, wol, HDV, DIMV);
    wconv_kernel<<<dim3(8*DIMV/32, DIMV/32, DEPTH), 256>>>(glu_w, wgh, wgl, DIMV, 8*DIMV);
    wconv_kernel<<<dim3(DIMV/32, 4*DIMV/32, DEPTH), 256>>>(ff2_w, wfh, wfl, 4*DIMV, DIMV);

    posmlp_kernel<<<2*SEQ - 1, PDIMV>>>(pw1, pb1, pw2, pb2, pw3, pb3, pbias);
    temp_kernel<<<BATCH, 256>>>(mask, temperature, tempbuf);

    for (int i = 0; i < DEPTH; i++) {
        // --- attention block ---
        ln_kernel<<<ROWS, 256>>>(x, ln1_g + i*DIMV, ln1_b + i*DIMV, hNh, hNl);
        tc_gemm<<<dim3(3*HDV/128, ROWS/128), 256, GSMEM>>>(
            hNh, hNl, wqh + (size_t)i*3*HDV*DIMV, wql + (size_t)i*3*HDV*DIMV,
            nullptr, nullptr, qkvbuf, 3*HDV, DIMV, 0);
        qkvnorm_kernel<<<(BATCH*SEQ*HEADS + 3)/4, 128>>>(qkvbuf, qb, kb, vb);
        attn_kernel<<<dim3(SEQ/64, HEADS, BATCH), 256, SMEM_ATTN>>>(
            qb, kb, vb, mask, pbias, tempbuf, oh, ol);
        tc_gemm<<<dim3(DIMV/128, ROWS/128), 256, GSMEM>>>(
            oh, ol, woh + (size_t)i*DIMV*HDV, wol + (size_t)i*DIMV*HDV,
            nullptr, x, x, DIMV, HDV, 2);
        // --- GLU FFN block ---
        ln_kernel<<<ROWS, 256>>>(x, ln2_g + i*DIMV, ln2_b + i*DIMV, hNh, hNl);
        tc_gemm<<<dim3(8*DIMV/128, ROWS/128), 256, GSMEM>>>(
            hNh, hNl, wgh + (size_t)i*8*DIMV*DIMV, wgl + (size_t)i*8*DIMV*DIMV,
            glu_b + (size_t)i*8*DIMV, nullptr, glubuf, 8*DIMV, DIMV, 1);
        glu_gate_kernel<<<(ROWS*4*DIMV + 255)/256, 256>>>(glubuf, gh, gl);
        tc_gemm<<<dim3(DIMV/128, ROWS/128), 256, GSMEM>>>(
            gh, gl, wfh + (size_t)i*4*DIMV*DIMV, wfl + (size_t)i*4*DIMV*DIMV,
            ff2_b + (size_t)i*DIMV, x, x, DIMV, 4*DIMV, 3);
    }
}